// round 9
// baseline (speedup 1.0000x reference)
#include <cuda_runtime.h>
#include <cuda_bf16.h>
#include <mma.h>
#include <cstdint>

using namespace nvcuda;

#define MAX_NODES_PAD 100096   // 782 * 128
#define MAX_EDGES 700000
#define D 128
#define D4 (D / 4)

// Scratch (device globals; rebuilt every replay)
__device__ int g_deg[MAX_NODES_PAD];
__device__ int g_rowstart[MAX_NODES_PAD];
__device__ int g_cursor[MAX_NODES_PAD];
__device__ int g_bsum[256];
__device__ int g_adj[2 * MAX_EDGES];
__device__ float g_Z[(size_t)MAX_NODES_PAD * D];            // X @ Wh
__device__ __nv_bfloat16 g_Hhi[(size_t)MAX_NODES_PAD * D];  // split relu(Zagg + bh)
__device__ __nv_bfloat16 g_Hlo[(size_t)MAX_NODES_PAD * D];

// ===========================================================================
// CSR build
// ===========================================================================
__global__ void zero_deg_kernel(int n) {
    int i = blockIdx.x * blockDim.x + threadIdx.x;
    if (i < n) g_deg[i] = 0;
}

__global__ void hist_kernel(const int* __restrict__ ra, const int* __restrict__ rb, int n_edges) {
    int e = blockIdx.x * blockDim.x + threadIdx.x;
    if (e >= n_edges) return;
    atomicAdd(&g_deg[ra[e]], 1);
    atomicAdd(&g_deg[rb[e]], 1);
}

__global__ void scan_block_kernel(int n) {
    __shared__ int wsum[32];
    int i = blockIdx.x * 1024 + threadIdx.x;
    int lane = threadIdx.x & 31, w = threadIdx.x >> 5;
    int v = (i < n) ? g_deg[i] : 0;
    int s = v;
    #pragma unroll
    for (int o = 1; o < 32; o <<= 1) {
        int t = __shfl_up_sync(0xFFFFFFFFu, s, o);
        if (lane >= o) s += t;
    }
    if (lane == 31) wsum[w] = s;
    __syncthreads();
    if (threadIdx.x < 32) {
        int t = wsum[threadIdx.x];
        int sc = t;
        #pragma unroll
        for (int o = 1; o < 32; o <<= 1) {
            int u = __shfl_up_sync(0xFFFFFFFFu, sc, o);
            if (lane >= o) sc += u;
        }
        wsum[threadIdx.x] = sc - t;
        if (threadIdx.x == 31) g_bsum[blockIdx.x] = sc;
    }
    __syncthreads();
    if (i < n) g_rowstart[i] = (s - v) + wsum[w];
}

__global__ void scan_top_kernel(int nb) {
    __shared__ int sm[256];
    int t = threadIdx.x;
    int v = (t < nb) ? g_bsum[t] : 0;
    sm[t] = v;
    __syncthreads();
    #pragma unroll
    for (int o = 1; o < 256; o <<= 1) {
        int u = (t >= o) ? sm[t - o] : 0;
        __syncthreads();
        sm[t] += u;
        __syncthreads();
    }
    if (t < nb) g_bsum[t] = sm[t] - v;
}

__global__ void scan_add_kernel(int n) {
    int i = blockIdx.x * 1024 + threadIdx.x;
    if (i < n) {
        int rs = g_rowstart[i] + g_bsum[blockIdx.x];
        g_rowstart[i] = rs;
        g_cursor[i] = rs;
    }
}

__global__ void fill_adj_kernel(const int* __restrict__ ra, const int* __restrict__ rb, int n_edges) {
    int e = blockIdx.x * blockDim.x + threadIdx.x;
    if (e >= n_edges) return;
    int a = ra[e], b = rb[e];
    int p = atomicAdd(&g_cursor[a], 1);
    g_adj[p] = b;
    int q = atomicAdd(&g_cursor[b], 1);
    g_adj[q] = a;
}

// ===========================================================================
// Shared GEMM plumbing
// ===========================================================================
#define LDA 136

__device__ __forceinline__ void split2(float x, __nv_bfloat16& hi, __nv_bfloat16& lo) {
    hi = __float2bfloat16_rn(x);
    lo = __float2bfloat16_rn(x - __bfloat162float(hi));
}

typedef wmma::fragment<wmma::matrix_a, 16, 16, 16, __nv_bfloat16, wmma::row_major> FragA;
typedef wmma::fragment<wmma::matrix_b, 16, 16, 16, __nv_bfloat16, wmma::row_major> FragB;
typedef wmma::fragment<wmma::accumulator, 16, 16, 16, float> FragC;

// ===========================================================================
// Kernel Z: Z = X @ Wh   (bf16x3, graph-independent; overlaps CSR build)
// 512 thr / 16 warps; warp tile 16 rows x 64 cols. Direct frag store to g_Z.
// ===========================================================================
#define SMZ_AHI 0
#define SMZ_ALO (128 * LDA * 2)
#define SMZ_WHI (2 * 128 * LDA * 2)
#define SMZ_WLO (3 * 128 * LDA * 2)
#define SMZ_TOTAL (4 * 128 * LDA * 2)   // 139264

__global__ __launch_bounds__(512, 1)
void zgemm_kernel(const float* __restrict__ X, const float* __restrict__ Wh, int n_nodes) {
    extern __shared__ char smem[];
    __nv_bfloat16* Ahi = (__nv_bfloat16*)(smem + SMZ_AHI);
    __nv_bfloat16* Alo = (__nv_bfloat16*)(smem + SMZ_ALO);
    __nv_bfloat16* Whi = (__nv_bfloat16*)(smem + SMZ_WHI);
    __nv_bfloat16* Wlo = (__nv_bfloat16*)(smem + SMZ_WLO);

    const int tid = threadIdx.x;
    const int wid = tid >> 5;
    const int row0 = blockIdx.x * 128;

    const float4* X4 = (const float4*)X;
    #pragma unroll
    for (int it = 0; it < 8; ++it) {
        int i = tid + it * 512;
        int r = i >> 5, c = (i & 31) * 4;
        float4 v = make_float4(0.f, 0.f, 0.f, 0.f);
        if (row0 + r < n_nodes) v = X4[(size_t)(row0 + r) * D4 + (c >> 2)];
        __nv_bfloat16 h0, l0, h1, l1, h2, l2, h3, l3;
        split2(v.x, h0, l0); split2(v.y, h1, l1);
        split2(v.z, h2, l2); split2(v.w, h3, l3);
        int o = r * LDA + c;
        Ahi[o] = h0; Ahi[o+1] = h1; Ahi[o+2] = h2; Ahi[o+3] = h3;
        Alo[o] = l0; Alo[o+1] = l1; Alo[o+2] = l2; Alo[o+3] = l3;
    }
    {
        const float4* W4 = (const float4*)Wh;
        #pragma unroll
        for (int it = 0; it < 8; ++it) {
            int i = tid + it * 512;
            int k = i >> 5, c = (i & 31) * 4;
            float4 v = W4[i];
            __nv_bfloat16 h0, l0, h1, l1, h2, l2, h3, l3;
            split2(v.x, h0, l0); split2(v.y, h1, l1);
            split2(v.z, h2, l2); split2(v.w, h3, l3);
            int o = k * LDA + c;
            Whi[o] = h0; Whi[o+1] = h1; Whi[o+2] = h2; Whi[o+3] = h3;
            Wlo[o] = l0; Wlo[o+1] = l1; Wlo[o+2] = l2; Wlo[o+3] = l3;
        }
    }
    __syncthreads();

    const int wr = wid >> 1;
    const int wc = wid & 1;

    FragC acc[4];
    #pragma unroll
    for (int n = 0; n < 4; ++n) wmma::fill_fragment(acc[n], 0.f);
    for (int k = 0; k < 8; ++k) {
        FragA a_hi, a_lo;
        wmma::load_matrix_sync(a_hi, Ahi + wr * 16 * LDA + k * 16, LDA);
        wmma::load_matrix_sync(a_lo, Alo + wr * 16 * LDA + k * 16, LDA);
        #pragma unroll
        for (int n = 0; n < 4; ++n) {
            int nc = wc * 64 + n * 16;
            FragB b_hi, b_lo;
            wmma::load_matrix_sync(b_hi, Whi + k * 16 * LDA + nc, LDA);
            wmma::mma_sync(acc[n], a_hi, b_hi, acc[n]);
            wmma::mma_sync(acc[n], a_lo, b_hi, acc[n]);
            wmma::load_matrix_sync(b_lo, Wlo + k * 16 * LDA + nc, LDA);
            wmma::mma_sync(acc[n], a_hi, b_lo, acc[n]);
        }
    }
    // g_Z padded to full tiles: unguarded direct store
    float* Zt = g_Z + (size_t)(row0 + wr * 16) * D + wc * 64;
    #pragma unroll
    for (int n = 0; n < 4; ++n)
        wmma::store_matrix_sync(Zt + n * 16, acc[n], D, wmma::mem_row_major);
}

// ===========================================================================
// Gather in Z-space + bias + relu + bf16 split.  Warp-per-node.
// ===========================================================================
__global__ __launch_bounds__(256)
void gather_kernel(const float* __restrict__ bh, int n_nodes) {
    int node = (blockIdx.x * blockDim.x + threadIdx.x) >> 5;
    int lane = threadIdx.x & 31;
    if (node >= n_nodes) return;

    const float4* Z4 = (const float4*)g_Z;
    float4 acc = Z4[(size_t)node * D4 + lane];
    int s = g_rowstart[node];
    int e = s + g_deg[node];
    int j = s;
    for (; j + 4 <= e; j += 4) {
        int n0 = g_adj[j + 0], n1 = g_adj[j + 1];
        int n2 = g_adj[j + 2], n3 = g_adj[j + 3];
        float4 v0 = Z4[(size_t)n0 * D4 + lane];
        float4 v1 = Z4[(size_t)n1 * D4 + lane];
        float4 v2 = Z4[(size_t)n2 * D4 + lane];
        float4 v3 = Z4[(size_t)n3 * D4 + lane];
        acc.x += (v0.x + v1.x) + (v2.x + v3.x);
        acc.y += (v0.y + v1.y) + (v2.y + v3.y);
        acc.z += (v0.z + v1.z) + (v2.z + v3.z);
        acc.w += (v0.w + v1.w) + (v2.w + v3.w);
    }
    for (; j < e; ++j) {
        int nb = g_adj[j];
        float4 v = Z4[(size_t)nb * D4 + lane];
        acc.x += v.x; acc.y += v.y; acc.z += v.z; acc.w += v.w;
    }

    const float4 b4 = ((const float4*)bh)[lane];
    float x0 = fmaxf(acc.x + b4.x, 0.f);
    float x1 = fmaxf(acc.y + b4.y, 0.f);
    float x2 = fmaxf(acc.z + b4.z, 0.f);
    float x3 = fmaxf(acc.w + b4.w, 0.f);

    __nv_bfloat16 h0, l0, h1, l1, h2, l2, h3, l3;
    split2(x0, h0, l0); split2(x1, h1, l1);
    split2(x2, h2, l2); split2(x3, h3, l3);

    size_t o = (size_t)node * D + lane * 4;
    __nv_bfloat162* Hh2 = (__nv_bfloat162*)(g_Hhi + o);
    __nv_bfloat162* Hl2 = (__nv_bfloat162*)(g_Hlo + o);
    Hh2[0] = __nv_bfloat162(h0, h1);
    Hh2[1] = __nv_bfloat162(h2, h3);
    Hl2[0] = __nv_bfloat162(l0, l1);
    Hl2[1] = __nv_bfloat162(l2, l3);
}

// ===========================================================================
// GEMM2: out = H @ Wo + bo.  A frags straight from gmem (g_Hhi/g_Hlo);
// bias via accumulator-fragment init; direct frag store (guarded tail CTA).
// ===========================================================================
#define SM2_WHI 0
#define SM2_WLO (128 * LDA * 2)
#define SM2_BIAS (2 * 128 * LDA * 2)           // 16 x 128 f32 replicated bias
#define SM2_TOTAL (SM2_BIAS + 16 * 128 * 4)    // 77824

__global__ __launch_bounds__(512, 1)
void gemm2_kernel(const float* __restrict__ Wo, const float* __restrict__ bo,
                  float* __restrict__ out, int n_nodes) {
    extern __shared__ char smem[];
    __nv_bfloat16* Whi = (__nv_bfloat16*)(smem + SM2_WHI);
    __nv_bfloat16* Wlo = (__nv_bfloat16*)(smem + SM2_WLO);
    float*         bias_s = (float*)(smem + SM2_BIAS);

    const int tid = threadIdx.x;
    const int wid = tid >> 5;
    const int row0 = blockIdx.x * 128;

    {
        const float4* W4 = (const float4*)Wo;
        #pragma unroll
        for (int it = 0; it < 8; ++it) {
            int i = tid + it * 512;
            int k = i >> 5, c = (i & 31) * 4;
            float4 v = W4[i];
            __nv_bfloat16 h0, l0, h1, l1, h2, l2, h3, l3;
            split2(v.x, h0, l0); split2(v.y, h1, l1);
            split2(v.z, h2, l2); split2(v.w, h3, l3);
            int o = k * LDA + c;
            Whi[o] = h0; Whi[o+1] = h1; Whi[o+2] = h2; Whi[o+3] = h3;
            Wlo[o] = l0; Wlo[o+1] = l1; Wlo[o+2] = l2; Wlo[o+3] = l3;
        }
    }
    #pragma unroll
    for (int it = 0; it < 4; ++it) {
        int i = tid + it * 512;            // 2048 = 16 x 128
        bias_s[i] = bo[i & 127];
    }
    __syncthreads();

    const int wr = wid >> 1;
    const int wc = wid & 1;

    FragC acc[4];
    #pragma unroll
    for (int n = 0; n < 4; ++n)
        wmma::load_matrix_sync(acc[n], bias_s + wc * 64 + n * 16, 128, wmma::mem_row_major);

    const __nv_bfloat16* Ah = g_Hhi + (size_t)(row0 + wr * 16) * D;
    const __nv_bfloat16* Al = g_Hlo + (size_t)(row0 + wr * 16) * D;
    for (int k = 0; k < 8; ++k) {
        FragA a_hi, a_lo;
        wmma::load_matrix_sync(a_hi, Ah + k * 16, D);
        wmma::load_matrix_sync(a_lo, Al + k * 16, D);
        #pragma unroll
        for (int n = 0; n < 4; ++n) {
            int nc = wc * 64 + n * 16;
            FragB b_hi, b_lo;
            wmma::load_matrix_sync(b_hi, Whi + k * 16 * LDA + nc, LDA);
            wmma::mma_sync(acc[n], a_hi, b_hi, acc[n]);
            wmma::mma_sync(acc[n], a_lo, b_hi, acc[n]);
            wmma::load_matrix_sync(b_lo, Wlo + k * 16 * LDA + nc, LDA);
            wmma::mma_sync(acc[n], a_hi, b_lo, acc[n]);
        }
    }

    if (row0 + 128 <= n_nodes) {
        // fast path: whole tile in-bounds, store straight from fragments
        float* Ot = out + (size_t)(row0 + wr * 16) * D + wc * 64;
        #pragma unroll
        for (int n = 0; n < 4; ++n)
            wmma::store_matrix_sync(Ot + n * 16, acc[n], D, wmma::mem_row_major);
    } else {
        // tail CTA: stage to SMEM (reuse W region), guarded copy
        __syncthreads();
        float* stage = (float*)(smem + SM2_WHI);   // 128*128*4 = 64KB <= 69632
        #pragma unroll
        for (int n = 0; n < 4; ++n)
            wmma::store_matrix_sync(stage + (wr * 16) * 128 + wc * 64 + n * 16,
                                    acc[n], 128, wmma::mem_row_major);
        __syncthreads();
        #pragma unroll
        for (int it = 0; it < 8; ++it) {
            int i = tid + it * 512;
            int r = i >> 5, c = (i & 31) * 4;
            if (row0 + r < n_nodes)
                *(float4*)&out[(size_t)(row0 + r) * D + c] = *(float4*)&stage[r * 128 + c];
        }
    }
}

// ===========================================================================
extern "C" void kernel_launch(void* const* d_in, const int* in_sizes, int n_in,
                              void* d_out, int out_size) {
    const float* X  = (const float*)d_in[0];
    const int*   ra = (const int*)  d_in[1];
    const int*   rb = (const int*)  d_in[2];
    const float* Wh = (const float*)d_in[3];
    const float* bh = (const float*)d_in[4];
    const float* Wo = (const float*)d_in[5];
    const float* bo = (const float*)d_in[6];
    float* out = (float*)d_out;

    const int n_nodes = in_sizes[0] / D;
    const int n_edges = in_sizes[1];
    const int nb = (n_nodes + 1023) / 1024;
    const int gb = (n_nodes + 127) / 128;

    cudaFuncSetAttribute(zgemm_kernel, cudaFuncAttributeMaxDynamicSharedMemorySize, SMZ_TOTAL);
    cudaFuncSetAttribute(gemm2_kernel, cudaFuncAttributeMaxDynamicSharedMemorySize, SM2_TOTAL);

    // Fork: Z = X@Wh runs concurrently with CSR build (graceful serial fallback).
    cudaStream_t s1 = nullptr;
    cudaEvent_t ev0 = nullptr, ev1 = nullptr;
    bool forked =
        (cudaStreamCreateWithFlags(&s1, cudaStreamNonBlocking) == cudaSuccess) &&
        (cudaEventCreateWithFlags(&ev0, cudaEventDisableTiming) == cudaSuccess) &&
        (cudaEventCreateWithFlags(&ev1, cudaEventDisableTiming) == cudaSuccess);

    if (forked) {
        cudaEventRecord(ev0, 0);
        cudaStreamWaitEvent(s1, ev0, 0);
        zgemm_kernel<<<gb, 512, SMZ_TOTAL, s1>>>(X, Wh, n_nodes);
        cudaEventRecord(ev1, s1);
    } else {
        zgemm_kernel<<<gb, 512, SMZ_TOTAL>>>(X, Wh, n_nodes);
    }

    // CSR build (default stream)
    zero_deg_kernel<<<(n_nodes + 255) / 256, 256>>>(n_nodes);
    hist_kernel<<<(n_edges + 255) / 256, 256>>>(ra, rb, n_edges);
    scan_block_kernel<<<nb, 1024>>>(n_nodes);
    scan_top_kernel<<<1, 256>>>(nb);
    scan_add_kernel<<<nb, 1024>>>(n_nodes);
    fill_adj_kernel<<<(n_edges + 255) / 256, 256>>>(ra, rb, n_edges);

    if (forked) cudaStreamWaitEvent((cudaStream_t)0, ev1, 0);

    // Gather in Z-space (+bias+relu+split)
    int gblocks = (int)(((size_t)n_nodes * 32 + 255) / 256);
    gather_kernel<<<gblocks, 256>>>(bh, n_nodes);

    // GEMM2
    gemm2_kernel<<<gb, 512, SM2_TOTAL>>>(Wo, bo, out, n_nodes);
}